// round 1
// baseline (speedup 1.0000x reference)
#include <cuda_runtime.h>

// ProbsNet: out = mean over 5 of (pX @ tmpX)
//   tmp0[i] = sum_d sigmoid(pB*(pBEV*BEV + ST0[i,d])) * W0[i,d]
//   tmp1[i] = sum_d sigmoid(pB*(pBEV*BEV + ST1[i,d])) * W1[i,d]
// Folded: out = sum_i c0[i]*tmp0[i] + c1[i]*tmp1[i]
//   c0 = calc_probs(probs0)/5 ; c1 = (calc_probs(probs1..4) summed)/5

#define D        131072
#define NROWS    84
#define VPR      (D / 4)            // 32768 float4 per row
#define NVEC     (NROWS * VPR)      // 2752512 float4 per (ST,W) pair
#define GRID     2368               // 148 SMs * 16
#define BLOCK    256

__device__ float g_coef[2 * NROWS];
__device__ float g_part[GRID];

// ---------------------------------------------------------------------------
// Kernel 1: compute folded per-row coefficients (tiny, 1 thread)
// ---------------------------------------------------------------------------
__device__ __forceinline__ void calc_probs_into(const float* __restrict__ logits,
                                                float scale, float* __restrict__ out,
                                                bool accumulate) {
    float m = fmaxf(fmaxf(logits[0], logits[1]), fmaxf(logits[2], logits[3]));
    float e0 = expf(logits[0] - m);
    float e1 = expf(logits[1] - m);
    float e2 = expf(logits[2] - m);
    float e3 = expf(logits[3] - m);
    float inv = 1.0f / (e0 + e1 + e2 + e3);
    float p[4] = {e0 * inv, e1 * inv, e2 * inv, e3 * inv};

    for (int i = 0; i < 4; i++) {
        float v = scale * p[i];
        int base = i * 21;
        out[base] = (accumulate ? out[base] : 0.0f) + v;            // p_i
        for (int j = 0; j < 4; j++) {
            int b2 = base + 1 + j * 5;
            float vij = v * p[j];
            out[b2] = (accumulate ? out[b2] : 0.0f) + vij;          // p_i p_j
            for (int k = 0; k < 4; k++) {
                int b3 = b2 + 1 + k;
                out[b3] = (accumulate ? out[b3] : 0.0f) + vij * p[k]; // p_i p_j p_k
            }
        }
    }
}

__global__ void coef_kernel(const float* __restrict__ probs0,
                            const float* __restrict__ probs1,
                            const float* __restrict__ probs2,
                            const float* __restrict__ probs3,
                            const float* __restrict__ probs4) {
    if (threadIdx.x == 0) {
        calc_probs_into(probs0, 0.2f, g_coef,          false);
        calc_probs_into(probs1, 0.2f, g_coef + NROWS,  false);
        calc_probs_into(probs2, 0.2f, g_coef + NROWS,  true);
        calc_probs_into(probs3, 0.2f, g_coef + NROWS,  true);
        calc_probs_into(probs4, 0.2f, g_coef + NROWS,  true);
    }
}

// ---------------------------------------------------------------------------
// Kernel 2: main streaming reduction. 176 MB of fp32 reads -> HBM-bound.
// Deterministic: fixed-shape block reduce, one slot per block.
// ---------------------------------------------------------------------------
__global__ void __launch_bounds__(BLOCK)
reduce_kernel(const float* __restrict__ BEV,
              const float* __restrict__ ST0, const float* __restrict__ W0,
              const float* __restrict__ ST1, const float* __restrict__ W1,
              const float* __restrict__ pBEV, const float* __restrict__ pB) {
    const float bev   = pBEV[0] * BEV[0];
    const float scale = pB[0];

    const float4* __restrict__ st0 = (const float4*)ST0;
    const float4* __restrict__ w0  = (const float4*)W0;
    const float4* __restrict__ st1 = (const float4*)ST1;
    const float4* __restrict__ w1  = (const float4*)W1;

    float acc = 0.0f;
    const int total = 2 * NVEC;
    for (int idx = blockIdx.x * BLOCK + threadIdx.x; idx < total; idx += GRID * BLOCK) {
        const float4* st;
        const float4* w;
        int v;
        float c;
        if (idx < NVEC) {
            v  = idx;
            st = st0; w = w0;
            c  = g_coef[v >> 15];                 // v / VPR
        } else {
            v  = idx - NVEC;
            st = st1; w = w1;
            c  = g_coef[NROWS + (v >> 15)];
        }
        float4 s4 = st[v];
        float4 w4 = w[v];
        float t;
        t  = w4.x * __fdividef(1.0f, 1.0f + __expf(-scale * (bev + s4.x)));
        t += w4.y * __fdividef(1.0f, 1.0f + __expf(-scale * (bev + s4.y)));
        t += w4.z * __fdividef(1.0f, 1.0f + __expf(-scale * (bev + s4.z)));
        t += w4.w * __fdividef(1.0f, 1.0f + __expf(-scale * (bev + s4.w)));
        acc += c * t;
    }

    // warp reduce
    for (int off = 16; off > 0; off >>= 1)
        acc += __shfl_down_sync(0xFFFFFFFFu, acc, off);

    __shared__ float sm[BLOCK / 32];
    int lane = threadIdx.x & 31;
    int wid  = threadIdx.x >> 5;
    if (lane == 0) sm[wid] = acc;
    __syncthreads();
    if (wid == 0) {
        float b = (lane < BLOCK / 32) ? sm[lane] : 0.0f;
        for (int off = 4; off > 0; off >>= 1)
            b += __shfl_down_sync(0xFFFFFFFFu, b, off);
        if (lane == 0) g_part[blockIdx.x] = b;
    }
}

// ---------------------------------------------------------------------------
// Kernel 3: final deterministic sum of per-block partials
// ---------------------------------------------------------------------------
__global__ void __launch_bounds__(BLOCK)
final_kernel(float* __restrict__ out) {
    float acc = 0.0f;
    for (int i = threadIdx.x; i < GRID; i += BLOCK)
        acc += g_part[i];
    for (int off = 16; off > 0; off >>= 1)
        acc += __shfl_down_sync(0xFFFFFFFFu, acc, off);
    __shared__ float sm[BLOCK / 32];
    int lane = threadIdx.x & 31;
    int wid  = threadIdx.x >> 5;
    if (lane == 0) sm[wid] = acc;
    __syncthreads();
    if (threadIdx.x == 0) {
        float s = 0.0f;
        for (int i = 0; i < BLOCK / 32; i++) s += sm[i];
        out[0] = s;
    }
}

// ---------------------------------------------------------------------------
// Launch. Input order (metadata): BEV, ST0, Weight0, ST1, Weight1, Problem,
// probs0..probs4, pBEV, pB
// ---------------------------------------------------------------------------
extern "C" void kernel_launch(void* const* d_in, const int* in_sizes, int n_in,
                              void* d_out, int out_size) {
    const float* BEV    = (const float*)d_in[0];
    const float* ST0    = (const float*)d_in[1];
    const float* W0     = (const float*)d_in[2];
    const float* ST1    = (const float*)d_in[3];
    const float* W1     = (const float*)d_in[4];
    // d_in[5] = Problem (int, unused)
    const float* probs0 = (const float*)d_in[6];
    const float* probs1 = (const float*)d_in[7];
    const float* probs2 = (const float*)d_in[8];
    const float* probs3 = (const float*)d_in[9];
    const float* probs4 = (const float*)d_in[10];
    const float* pBEV   = (const float*)d_in[11];
    const float* pB     = (const float*)d_in[12];
    float* out = (float*)d_out;

    coef_kernel<<<1, 32>>>(probs0, probs1, probs2, probs3, probs4);
    reduce_kernel<<<GRID, BLOCK>>>(BEV, ST0, W0, ST1, W1, pBEV, pB);
    final_kernel<<<1, BLOCK>>>(out);
}